// round 6
// baseline (speedup 1.0000x reference)
#include <cuda_runtime.h>
#include <cuda_bf16.h>
#include <cstdint>

// ---------------------------------------------------------------------------
// ResidualGatedGCN — fused pipeline, tf32 mma.sync
//   node_gemm:  proj = nf@W+b ; h-cols -> out directly, QKV -> g_qkv[50000,384]
//   edge_fused: ep = ef@We+be (SMEM only) ; out[r] += sigmoid(Q[r]+K[s]+ep)*V[s]
// ---------------------------------------------------------------------------

#define N_NODES 50000
#define N_EDGES 600000

__device__ float g_qkv[(size_t)N_NODES * 384];      // 76.8 MB (fits L2)

#define KC      32
#define APAD    36
#define BPAD    132
#define A_CHUNK_BYTES (128 * APAD * 4)   // 18432
#define B_BYTES       (128 * BPAD * 4)   // 67584
#define GEMM_SMEM     (B_BYTES + 2 * A_CHUNK_BYTES)   // 104448 -> 2 CTAs/SM

__device__ __forceinline__ uint32_t smem_u32(const void* p) {
    uint32_t a;
    asm("{ .reg .u64 t; cvta.to.shared.u64 t, %1; cvt.u32.u64 %0, t; }"
        : "=r"(a) : "l"(p));
    return a;
}
__device__ __forceinline__ uint32_t f2tf32(float f) {
    uint32_t u;
    asm("cvt.rna.tf32.f32 %0, %1;" : "=r"(u) : "f"(f));
    return u;
}
__device__ __forceinline__ void mma_tf32(float& d0, float& d1, float& d2, float& d3,
                                         uint32_t a0, uint32_t a1, uint32_t a2, uint32_t a3,
                                         uint32_t b0, uint32_t b1)
{
    asm volatile(
        "mma.sync.aligned.m16n8k8.row.col.f32.tf32.tf32.f32 "
        "{%0,%1,%2,%3}, {%4,%5,%6,%7}, {%8,%9}, {%0,%1,%2,%3};"
        : "+f"(d0), "+f"(d1), "+f"(d2), "+f"(d3)
        : "r"(a0), "r"(a1), "r"(a2), "r"(a3), "r"(b0), "r"(b1));
}
__device__ __forceinline__ void cp_async16(uint32_t sdst, const void* gsrc, int bytes) {
    asm volatile("cp.async.cg.shared.global [%0], [%1], 16, %2;"
                 :: "r"(sdst), "l"(gsrc), "r"(bytes));
}
__device__ __forceinline__ void cp_commit() {
    asm volatile("cp.async.commit_group;" ::: "memory");
}
__device__ __forceinline__ float sigmoidf_(float x) {
    return 1.0f / (1.0f + __expf(-x));
}

// ===========================================================================
// Node GEMM: C tile [128,128] = nf[row0:+128, :] @ W[:, colW0:+128] + bias
// bx==0 -> write `out` (stride 128); bx>0 -> write g_qkv (stride 384).
// ===========================================================================
__global__ __launch_bounds__(256, 2)
void node_gemm(const float* __restrict__ A,
               const float* __restrict__ W,
               const float* __restrict__ bias,
               float* __restrict__ out_h,
               float* __restrict__ qkv)
{
    extern __shared__ char smem[];
    uint32_t* Bs = (uint32_t*)smem;
    float* Abuf[2] = { (float*)(smem + B_BYTES),
                       (float*)(smem + B_BYTES + A_CHUNK_BYTES) };
    const uint32_t sbase = smem_u32(smem);
    const uint32_t a_s[2] = { sbase + B_BYTES, sbase + B_BYTES + A_CHUNK_BYTES };

    const int tid   = threadIdx.x;
    const int row0  = blockIdx.y * 128;
    const int colW0 = blockIdx.x * 128;
    const int M     = N_NODES;

    auto copyA = [&](int chunk, uint32_t sdst) {
        #pragma unroll
        for (int j = 0; j < 4; j++) {
            const int idx = tid + j * 256;
            const int r   = idx >> 3;
            const int seg = idx & 7;
            const int gr  = row0 + r;
            const int bytes = (gr < M) ? 16 : 0;
            const int grc = (gr < M) ? gr : (M - 1);
            cp_async16(sdst + (r * APAD + seg * 4) * 4,
                       A + (size_t)grc * 128 + chunk * KC + seg * 4, bytes);
        }
    };

    copyA(0, a_s[0]); cp_commit();

    #pragma unroll
    for (int it = 0; it < 16; it++) {
        const int idx = tid + it * 256;
        const int k   = idx >> 5;
        const int n4  = (idx & 31) * 4;
        const float4 v = *(const float4*)&W[(size_t)k * 512 + colW0 + n4];
        uint4 o;
        o.x = f2tf32(v.x); o.y = f2tf32(v.y); o.z = f2tf32(v.z); o.w = f2tf32(v.w);
        *(uint4*)&Bs[k * BPAD + n4] = o;
    }

    copyA(1, a_s[1]); cp_commit();

    const int wid  = tid >> 5;
    const int lane = tid & 31;
    const int g    = lane >> 2;
    const int t    = lane & 3;
    const int wm   = wid >> 1;
    const int wn   = wid & 1;

    float acc[2][8][4];
    #pragma unroll
    for (int m = 0; m < 2; m++)
        #pragma unroll
        for (int n = 0; n < 8; n++)
            #pragma unroll
            for (int j = 0; j < 4; j++) acc[m][n][j] = 0.f;

    auto compute_chunk = [&](const float* __restrict__ Ab, int kb) {
        #pragma unroll
        for (int ks = 0; ks < 4; ks++) {
            const int k0 = ks * 8;
            uint32_t af[2][4];
            #pragma unroll
            for (int m = 0; m < 2; m++) {
                const int rb = wm * 32 + m * 16 + g;
                const float* p0 = Ab + rb * APAD + k0 + t;
                const float* p1 = Ab + (rb + 8) * APAD + k0 + t;
                af[m][0] = f2tf32(p0[0]);
                af[m][1] = f2tf32(p1[0]);
                af[m][2] = f2tf32(p0[4]);
                af[m][3] = f2tf32(p1[4]);
            }
            #pragma unroll
            for (int n = 0; n < 8; n++) {
                const int nidx = wn * 64 + n * 8 + g;
                const uint32_t b0 = Bs[(kb + k0 + t) * BPAD + nidx];
                const uint32_t b1 = Bs[(kb + k0 + t + 4) * BPAD + nidx];
                #pragma unroll
                for (int m = 0; m < 2; m++)
                    mma_tf32(acc[m][n][0], acc[m][n][1], acc[m][n][2], acc[m][n][3],
                             af[m][0], af[m][1], af[m][2], af[m][3], b0, b1);
            }
        }
    };

    asm volatile("cp.async.wait_group 1;" ::: "memory");
    __syncthreads();
    compute_chunk(Abuf[0], 0);
    __syncthreads();
    copyA(2, a_s[0]); cp_commit();

    asm volatile("cp.async.wait_group 1;" ::: "memory");
    __syncthreads();
    compute_chunk(Abuf[1], 32);
    __syncthreads();
    copyA(3, a_s[1]); cp_commit();

    asm volatile("cp.async.wait_group 1;" ::: "memory");
    __syncthreads();
    compute_chunk(Abuf[0], 64);

    asm volatile("cp.async.wait_group 0;" ::: "memory");
    __syncthreads();
    compute_chunk(Abuf[1], 96);

    // epilogue: bias + store to out (h) or qkv
    float2 bvs[8];
    #pragma unroll
    for (int n = 0; n < 8; n++)
        bvs[n] = *(const float2*)&bias[colW0 + wn * 64 + n * 8 + 2 * t];

    float* C;
    int Cstride, colC0;
    if (blockIdx.x == 0) { C = out_h; Cstride = 128; colC0 = 0; }
    else                 { C = qkv;   Cstride = 384; colC0 = colW0 - 128; }

    #pragma unroll
    for (int m = 0; m < 2; m++) {
        const int r0 = row0 + wm * 32 + m * 16 + g;
        const int r1 = r0 + 8;
        #pragma unroll
        for (int n = 0; n < 8; n++) {
            const int cc = colC0 + wn * 64 + n * 8 + 2 * t;
            if (r0 < M)
                *(float2*)&C[(size_t)r0 * Cstride + cc] =
                    make_float2(acc[m][n][0] + bvs[n].x, acc[m][n][1] + bvs[n].y);
            if (r1 < M)
                *(float2*)&C[(size_t)r1 * Cstride + cc] =
                    make_float2(acc[m][n][2] + bvs[n].x, acc[m][n][3] + bvs[n].y);
        }
    }
}

// ===========================================================================
// Fused edge kernel: per CTA, 128 edges.
//   ep = ef[e0:+128, :] @ We + be      (tf32 MMA, result kept in SMEM)
//   out[rcv] += sigmoid(Q[rcv] + K[snd] + ep) * V[snd]
// ===========================================================================
__global__ __launch_bounds__(256, 2)
void edge_fused(const float* __restrict__ ef,
                const float* __restrict__ We,
                const float* __restrict__ Web,
                const int*   __restrict__ snd,
                const int*   __restrict__ rcv,
                const float* __restrict__ qkv,
                float* __restrict__ out)
{
    extern __shared__ char smem[];
    uint32_t* Bs   = (uint32_t*)smem;                 // We (tf32), then reused as ep_s
    float*    ep_s = (float*)smem;                    // [128][BPAD] after MMA
    float* Abuf[2] = { (float*)(smem + B_BYTES),
                       (float*)(smem + B_BYTES + A_CHUNK_BYTES) };
    const uint32_t sbase = smem_u32(smem);
    const uint32_t a_s[2] = { sbase + B_BYTES, sbase + B_BYTES + A_CHUNK_BYTES };

    const int tid  = threadIdx.x;
    const int row0 = blockIdx.x * 128;                // edge base
    const int M    = N_EDGES;

    auto copyA = [&](int chunk, uint32_t sdst) {
        #pragma unroll
        for (int j = 0; j < 4; j++) {
            const int idx = tid + j * 256;
            const int r   = idx >> 3;
            const int seg = idx & 7;
            const int gr  = row0 + r;
            const int bytes = (gr < M) ? 16 : 0;
            const int grc = (gr < M) ? gr : (M - 1);
            cp_async16(sdst + (r * APAD + seg * 4) * 4,
                       ef + (size_t)grc * 128 + chunk * KC + seg * 4, bytes);
        }
    };

    copyA(0, a_s[0]); cp_commit();

    #pragma unroll
    for (int it = 0; it < 16; it++) {
        const int idx = tid + it * 256;
        const int k   = idx >> 5;
        const int n4  = (idx & 31) * 4;
        const float4 v = *(const float4*)&We[(size_t)k * 128 + n4];
        uint4 o;
        o.x = f2tf32(v.x); o.y = f2tf32(v.y); o.z = f2tf32(v.z); o.w = f2tf32(v.w);
        *(uint4*)&Bs[k * BPAD + n4] = o;
    }

    copyA(1, a_s[1]); cp_commit();

    const int wid  = tid >> 5;
    const int lane = tid & 31;
    const int g    = lane >> 2;
    const int t    = lane & 3;
    const int wm   = wid >> 1;
    const int wn   = wid & 1;

    float acc[2][8][4];
    #pragma unroll
    for (int m = 0; m < 2; m++)
        #pragma unroll
        for (int n = 0; n < 8; n++)
            #pragma unroll
            for (int j = 0; j < 4; j++) acc[m][n][j] = 0.f;

    auto compute_chunk = [&](const float* __restrict__ Ab, int kb) {
        #pragma unroll
        for (int ks = 0; ks < 4; ks++) {
            const int k0 = ks * 8;
            uint32_t af[2][4];
            #pragma unroll
            for (int m = 0; m < 2; m++) {
                const int rb = wm * 32 + m * 16 + g;
                const float* p0 = Ab + rb * APAD + k0 + t;
                const float* p1 = Ab + (rb + 8) * APAD + k0 + t;
                af[m][0] = f2tf32(p0[0]);
                af[m][1] = f2tf32(p1[0]);
                af[m][2] = f2tf32(p0[4]);
                af[m][3] = f2tf32(p1[4]);
            }
            #pragma unroll
            for (int n = 0; n < 8; n++) {
                const int nidx = wn * 64 + n * 8 + g;
                const uint32_t b0 = Bs[(kb + k0 + t) * BPAD + nidx];
                const uint32_t b1 = Bs[(kb + k0 + t + 4) * BPAD + nidx];
                #pragma unroll
                for (int m = 0; m < 2; m++)
                    mma_tf32(acc[m][n][0], acc[m][n][1], acc[m][n][2], acc[m][n][3],
                             af[m][0], af[m][1], af[m][2], af[m][3], b0, b1);
            }
        }
    };

    asm volatile("cp.async.wait_group 1;" ::: "memory");
    __syncthreads();
    compute_chunk(Abuf[0], 0);
    __syncthreads();
    copyA(2, a_s[0]); cp_commit();

    asm volatile("cp.async.wait_group 1;" ::: "memory");
    __syncthreads();
    compute_chunk(Abuf[1], 32);
    __syncthreads();
    copyA(3, a_s[1]); cp_commit();

    asm volatile("cp.async.wait_group 1;" ::: "memory");
    __syncthreads();
    compute_chunk(Abuf[0], 64);

    asm volatile("cp.async.wait_group 0;" ::: "memory");
    __syncthreads();
    compute_chunk(Abuf[1], 96);

    // ---- park ep (+bias) in SMEM, reusing the B region ----
    __syncthreads();            // everyone done reading Bs
    float2 bvs[8];
    #pragma unroll
    for (int n = 0; n < 8; n++)
        bvs[n] = *(const float2*)&Web[wn * 64 + n * 8 + 2 * t];

    #pragma unroll
    for (int m = 0; m < 2; m++) {
        const int r0l = wm * 32 + m * 16 + g;
        #pragma unroll
        for (int n = 0; n < 8; n++) {
            const int cc = wn * 64 + n * 8 + 2 * t;
            *(float2*)&ep_s[r0l * BPAD + cc] =
                make_float2(acc[m][n][0] + bvs[n].x, acc[m][n][1] + bvs[n].y);
            *(float2*)&ep_s[(r0l + 8) * BPAD + cc] =
                make_float2(acc[m][n][2] + bvs[n].x, acc[m][n][3] + bvs[n].y);
        }
    }
    __syncthreads();

    // ---- gather + sigmoid + scatter: warp per edge, 16 edges per warp ----
    const int d = lane * 4;
    #pragma unroll 2
    for (int i = 0; i < 16; i++) {
        const int el = wid * 16 + i;
        const int e  = row0 + el;
        if (e >= M) break;
        const int s = __ldg(&snd[e]);
        const int r = __ldg(&rcv[e]);

        const float4 epv = *(const float4*)&ep_s[el * BPAD + d];
        const float4 q   = *(const float4*)&qkv[(size_t)r * 384 + d];
        const float4 kk  = *(const float4*)&qkv[(size_t)s * 384 + 128 + d];
        const float4 v   = *(const float4*)&qkv[(size_t)s * 384 + 256 + d];

        float4 msg;
        msg.x = sigmoidf_(q.x + kk.x + epv.x) * v.x;
        msg.y = sigmoidf_(q.y + kk.y + epv.y) * v.y;
        msg.z = sigmoidf_(q.z + kk.z + epv.z) * v.z;
        msg.w = sigmoidf_(q.w + kk.w + epv.w) * v.w;

        float* o = &out[(size_t)r * 128 + d];
        asm volatile("red.global.add.v4.f32 [%0], {%1,%2,%3,%4};"
                     :: "l"(o), "f"(msg.x), "f"(msg.y), "f"(msg.z), "f"(msg.w)
                     : "memory");
    }
}

// ---------------------------------------------------------------------------
// Launch
// Inputs: 0 nf[50000,128] 1 snd[600000] 2 rcv[600000] 3 ef[600000,128]
//         4 Wk[128,512] 5 Wb[512] 6 Wek[128,128] 7 Web[128]
// ---------------------------------------------------------------------------
extern "C" void kernel_launch(void* const* d_in, const int* in_sizes, int n_in,
                              void* d_out, int out_size)
{
    const float* nf   = (const float*)d_in[0];
    const int*   snd  = (const int*)  d_in[1];
    const int*   rcv  = (const int*)  d_in[2];
    const float* ef   = (const float*)d_in[3];
    const float* Wk   = (const float*)d_in[4];
    const float* Wb   = (const float*)d_in[5];
    const float* Wek  = (const float*)d_in[6];
    const float* Web  = (const float*)d_in[7];
    float* out = (float*)d_out;

    float* qkv_ptr;
    cudaGetSymbolAddress((void**)&qkv_ptr, g_qkv);

    cudaFuncSetAttribute(node_gemm,
                         cudaFuncAttributeMaxDynamicSharedMemorySize, GEMM_SMEM);
    cudaFuncSetAttribute(edge_fused,
                         cudaFuncAttributeMaxDynamicSharedMemorySize, GEMM_SMEM);

    // 1) node projection: h -> out, QKV -> g_qkv
    {
        dim3 grid(4, (N_NODES + 127) / 128);
        node_gemm<<<grid, 256, GEMM_SMEM>>>(nf, Wk, Wb, out, qkv_ptr);
    }
    // 2) fused edge projection + gated scatter
    {
        int blocks = (N_EDGES + 127) / 128;
        edge_fused<<<blocks, 256, GEMM_SMEM>>>(ef, Wek, Web, snd, rcv, qkv_ptr, out);
    }
}

// round 7
// speedup vs baseline: 1.1861x; 1.1861x over previous
#include <cuda_runtime.h>
#include <cuda_bf16.h>
#include <cstdint>

// ---------------------------------------------------------------------------
// ResidualGatedGCN — separate tf32 GEMMs + scatter, L2-aware data layout
//   node_gemm:  h-cols -> out directly, QKV -> g_qkv[50000,384] (L2-resident)
//   edge gemm:  ep = ef@We+be -> g_ep (streaming stores, evict-first)
//   scatter:    out[r] += sigmoid(Q[r]+K[s]+ep)*V[s]   (ep loads evict-first)
// ---------------------------------------------------------------------------

#define N_NODES 50000
#define N_EDGES 600000

__device__ float g_qkv[(size_t)N_NODES * 384];      // 76.8 MB
__device__ float g_ep [(size_t)N_EDGES * 128];      // 307.2 MB

#define KC      32
#define APAD    36
#define BPAD    132
#define A_CHUNK_BYTES (128 * APAD * 4)   // 18432
#define B_BYTES       (128 * BPAD * 4)   // 67584
#define GEMM_SMEM     (B_BYTES + 2 * A_CHUNK_BYTES)   // 104448

__device__ __forceinline__ uint32_t f2tf32(float f) {
    uint32_t u;
    asm("cvt.rna.tf32.f32 %0, %1;" : "=r"(u) : "f"(f));
    return u;
}
__device__ __forceinline__ void mma_tf32(float& d0, float& d1, float& d2, float& d3,
                                         uint32_t a0, uint32_t a1, uint32_t a2, uint32_t a3,
                                         uint32_t b0, uint32_t b1)
{
    asm volatile(
        "mma.sync.aligned.m16n8k8.row.col.f32.tf32.tf32.f32 "
        "{%0,%1,%2,%3}, {%4,%5,%6,%7}, {%8,%9}, {%0,%1,%2,%3};"
        : "+f"(d0), "+f"(d1), "+f"(d2), "+f"(d3)
        : "r"(a0), "r"(a1), "r"(a2), "r"(a3), "r"(b0), "r"(b1));
}
__device__ __forceinline__ uint32_t smem_u32(const void* p) {
    uint32_t a;
    asm("{ .reg .u64 t; cvta.to.shared.u64 t, %1; cvt.u32.u64 %0, t; }"
        : "=r"(a) : "l"(p));
    return a;
}
__device__ __forceinline__ void cp_async16(uint32_t sdst, const void* gsrc, int bytes) {
    asm volatile("cp.async.cg.shared.global [%0], [%1], 16, %2;"
                 :: "r"(sdst), "l"(gsrc), "r"(bytes));
}
__device__ __forceinline__ void cp_commit() {
    asm volatile("cp.async.commit_group;" ::: "memory");
}
__device__ __forceinline__ void st_cs_f2(float* p, float x, float y) {
    asm volatile("st.global.cs.v2.f32 [%0], {%1,%2};" :: "l"(p), "f"(x), "f"(y) : "memory");
}
__device__ __forceinline__ float4 ld_cs_f4(const float* p) {
    float4 v;
    asm volatile("ld.global.cs.v4.f32 {%0,%1,%2,%3}, [%4];"
                 : "=f"(v.x), "=f"(v.y), "=f"(v.z), "=f"(v.w) : "l"(p));
    return v;
}
__device__ __forceinline__ float sigmoidf_(float x) {
    return 1.0f / (1.0f + __expf(-x));
}

// ===========================================================================
// Generic tf32 tile GEMM body (128x128 tile, K=128), used by both kernels.
// STREAM_C: use st.global.cs for C stores.
// ===========================================================================
template <bool STREAM_C>
__device__ __forceinline__
void gemm_tile(const float* __restrict__ A, int M, int Wstride,
               const float* __restrict__ W, const float* __restrict__ bias,
               float* __restrict__ C, int Cstride,
               int row0, int colW0, int colC0, char* smem)
{
    uint32_t* Bs = (uint32_t*)smem;
    float* Abuf[2] = { (float*)(smem + B_BYTES),
                       (float*)(smem + B_BYTES + A_CHUNK_BYTES) };
    const uint32_t sbase = smem_u32(smem);
    const uint32_t a_s[2] = { sbase + B_BYTES, sbase + B_BYTES + A_CHUNK_BYTES };

    const int tid = threadIdx.x;

    auto copyA = [&](int chunk, uint32_t sdst) {
        #pragma unroll
        for (int j = 0; j < 4; j++) {
            const int idx = tid + j * 256;
            const int r   = idx >> 3;
            const int seg = idx & 7;
            const int gr  = row0 + r;
            const int bytes = (gr < M) ? 16 : 0;
            const int grc = (gr < M) ? gr : (M - 1);
            cp_async16(sdst + (r * APAD + seg * 4) * 4,
                       A + (size_t)grc * 128 + chunk * KC + seg * 4, bytes);
        }
    };

    copyA(0, a_s[0]); cp_commit();

    #pragma unroll
    for (int it = 0; it < 16; it++) {
        const int idx = tid + it * 256;
        const int k   = idx >> 5;
        const int n4  = (idx & 31) * 4;
        const float4 v = *(const float4*)&W[(size_t)k * Wstride + colW0 + n4];
        uint4 o;
        o.x = f2tf32(v.x); o.y = f2tf32(v.y); o.z = f2tf32(v.z); o.w = f2tf32(v.w);
        *(uint4*)&Bs[k * BPAD + n4] = o;
    }

    copyA(1, a_s[1]); cp_commit();

    const int wid  = tid >> 5;
    const int lane = tid & 31;
    const int g    = lane >> 2;
    const int t    = lane & 3;
    const int wm   = wid >> 1;
    const int wn   = wid & 1;

    float acc[2][8][4];
    #pragma unroll
    for (int m = 0; m < 2; m++)
        #pragma unroll
        for (int n = 0; n < 8; n++)
            #pragma unroll
            for (int j = 0; j < 4; j++) acc[m][n][j] = 0.f;

    auto compute_chunk = [&](const float* __restrict__ Ab, int kb) {
        #pragma unroll
        for (int ks = 0; ks < 4; ks++) {
            const int k0 = ks * 8;
            uint32_t af[2][4];
            #pragma unroll
            for (int m = 0; m < 2; m++) {
                const int rb = wm * 32 + m * 16 + g;
                const float* p0 = Ab + rb * APAD + k0 + t;
                const float* p1 = Ab + (rb + 8) * APAD + k0 + t;
                af[m][0] = f2tf32(p0[0]);
                af[m][1] = f2tf32(p1[0]);
                af[m][2] = f2tf32(p0[4]);
                af[m][3] = f2tf32(p1[4]);
            }
            #pragma unroll
            for (int n = 0; n < 8; n++) {
                const int nidx = wn * 64 + n * 8 + g;
                const uint32_t b0 = Bs[(kb + k0 + t) * BPAD + nidx];
                const uint32_t b1 = Bs[(kb + k0 + t + 4) * BPAD + nidx];
                #pragma unroll
                for (int m = 0; m < 2; m++)
                    mma_tf32(acc[m][n][0], acc[m][n][1], acc[m][n][2], acc[m][n][3],
                             af[m][0], af[m][1], af[m][2], af[m][3], b0, b1);
            }
        }
    };

    asm volatile("cp.async.wait_group 1;" ::: "memory");
    __syncthreads();
    compute_chunk(Abuf[0], 0);
    __syncthreads();
    copyA(2, a_s[0]); cp_commit();

    asm volatile("cp.async.wait_group 1;" ::: "memory");
    __syncthreads();
    compute_chunk(Abuf[1], 32);
    __syncthreads();
    copyA(3, a_s[1]); cp_commit();

    asm volatile("cp.async.wait_group 1;" ::: "memory");
    __syncthreads();
    compute_chunk(Abuf[0], 64);

    asm volatile("cp.async.wait_group 0;" ::: "memory");
    __syncthreads();
    compute_chunk(Abuf[1], 96);

    float2 bvs[8];
    #pragma unroll
    for (int n = 0; n < 8; n++)
        bvs[n] = *(const float2*)&bias[colW0 + wn * 64 + n * 8 + 2 * t];

    #pragma unroll
    for (int m = 0; m < 2; m++) {
        const int r0 = row0 + wm * 32 + m * 16 + g;
        const int r1 = r0 + 8;
        #pragma unroll
        for (int n = 0; n < 8; n++) {
            const int cc = colC0 + wn * 64 + n * 8 + 2 * t;
            if (r0 < M) {
                float* p = &C[(size_t)r0 * Cstride + cc];
                if (STREAM_C) st_cs_f2(p, acc[m][n][0] + bvs[n].x, acc[m][n][1] + bvs[n].y);
                else *(float2*)p = make_float2(acc[m][n][0] + bvs[n].x,
                                               acc[m][n][1] + bvs[n].y);
            }
            if (r1 < M) {
                float* p = &C[(size_t)r1 * Cstride + cc];
                if (STREAM_C) st_cs_f2(p, acc[m][n][2] + bvs[n].x, acc[m][n][3] + bvs[n].y);
                else *(float2*)p = make_float2(acc[m][n][2] + bvs[n].x,
                                               acc[m][n][3] + bvs[n].y);
            }
        }
    }
}

// Node projection: bx==0 -> h into out (stride 128); bx>0 -> QKV into g_qkv.
__global__ __launch_bounds__(256, 2)
void node_gemm(const float* __restrict__ nf,
               const float* __restrict__ Wk,
               const float* __restrict__ Wb,
               float* __restrict__ out,
               float* __restrict__ qkv)
{
    extern __shared__ char smem[];
    const int row0  = blockIdx.y * 128;
    const int colW0 = blockIdx.x * 128;
    if (blockIdx.x == 0)
        gemm_tile<false>(nf, N_NODES, 512, Wk, Wb, out, 128, row0, 0, 0, smem);
    else
        gemm_tile<false>(nf, N_NODES, 512, Wk, Wb, qkv, 384, row0, colW0, colW0 - 128, smem);
}

// Edge projection: ep = ef @ We + be, streaming stores.
__global__ __launch_bounds__(256, 2)
void edge_gemm(const float* __restrict__ ef,
               const float* __restrict__ Wek,
               const float* __restrict__ Web,
               float* __restrict__ ep)
{
    extern __shared__ char smem[];
    gemm_tile<true>(ef, N_EDGES, 128, Wek, Web, ep, 128, blockIdx.x * 128, 0, 0, smem);
}

// ---------------------------------------------------------------------------
// Scatter: one warp per edge. ep loads evict-first; qkv gathers stay in L2.
// ---------------------------------------------------------------------------
__global__ __launch_bounds__(256)
void edge_scatter_kernel(const int* __restrict__ senders,
                         const int* __restrict__ receivers,
                         const float* __restrict__ qkv,
                         const float* __restrict__ ep,
                         float* __restrict__ out)
{
    const int warp = (blockIdx.x * blockDim.x + threadIdx.x) >> 5;
    const int lane = threadIdx.x & 31;
    if (warp >= N_EDGES) return;
    const int e = warp;

    const int s = __ldg(&senders[e]);
    const int r = __ldg(&receivers[e]);
    const int d = lane * 4;

    const float4 epv = ld_cs_f4(&ep[(size_t)e * 128 + d]);
    const float4 q   = *(const float4*)&qkv[(size_t)r * 384 + d];
    const float4 kk  = *(const float4*)&qkv[(size_t)s * 384 + 128 + d];
    const float4 v   = *(const float4*)&qkv[(size_t)s * 384 + 256 + d];

    float4 m;
    m.x = sigmoidf_(q.x + kk.x + epv.x) * v.x;
    m.y = sigmoidf_(q.y + kk.y + epv.y) * v.y;
    m.z = sigmoidf_(q.z + kk.z + epv.z) * v.z;
    m.w = sigmoidf_(q.w + kk.w + epv.w) * v.w;

    float* o = &out[(size_t)r * 128 + d];
    asm volatile("red.global.add.v4.f32 [%0], {%1,%2,%3,%4};"
                 :: "l"(o), "f"(m.x), "f"(m.y), "f"(m.z), "f"(m.w)
                 : "memory");
}

// ---------------------------------------------------------------------------
// Launch
// Inputs: 0 nf[50000,128] 1 snd[600000] 2 rcv[600000] 3 ef[600000,128]
//         4 Wk[128,512] 5 Wb[512] 6 Wek[128,128] 7 Web[128]
// ---------------------------------------------------------------------------
extern "C" void kernel_launch(void* const* d_in, const int* in_sizes, int n_in,
                              void* d_out, int out_size)
{
    const float* nf   = (const float*)d_in[0];
    const int*   snd  = (const int*)  d_in[1];
    const int*   rcv  = (const int*)  d_in[2];
    const float* ef   = (const float*)d_in[3];
    const float* Wk   = (const float*)d_in[4];
    const float* Wb   = (const float*)d_in[5];
    const float* Wek  = (const float*)d_in[6];
    const float* Web  = (const float*)d_in[7];
    float* out = (float*)d_out;

    float* qkv_ptr;
    float* ep_ptr;
    cudaGetSymbolAddress((void**)&qkv_ptr, g_qkv);
    cudaGetSymbolAddress((void**)&ep_ptr,  g_ep);

    cudaFuncSetAttribute(node_gemm,
                         cudaFuncAttributeMaxDynamicSharedMemorySize, GEMM_SMEM);
    cudaFuncSetAttribute(edge_gemm,
                         cudaFuncAttributeMaxDynamicSharedMemorySize, GEMM_SMEM);

    // 1) node projection: h -> out, QKV -> g_qkv
    {
        dim3 grid(4, (N_NODES + 127) / 128);
        node_gemm<<<grid, 256, GEMM_SMEM>>>(nf, Wk, Wb, out, qkv_ptr);
    }
    // 2) edge projection -> g_ep (streaming)
    {
        int blocks = (N_EDGES + 127) / 128;
        edge_gemm<<<blocks, 256, GEMM_SMEM>>>(ef, Wek, Web, ep_ptr);
    }
    // 3) gated scatter
    {
        int blocks = (N_EDGES * 32 + 255) / 256;
        edge_scatter_kernel<<<blocks, 256>>>(snd, rcv, qkv_ptr, ep_ptr, out);
    }
}

// round 8
// speedup vs baseline: 1.2213x; 1.0297x over previous
#include <cuda_runtime.h>
#include <cuda_bf16.h>
#include <cstdint>

// ---------------------------------------------------------------------------
// ResidualGatedGCN — node tf32 GEMM + fused edge GEMM/scatter (ILP-batched)
//   node_gemm:  h-cols -> out directly, QKV -> g_qkv[50000,384]
//   edge_fused: ep = ef@We+be (SMEM only); out[r] += sigmoid(Q[r]+K[s]+ep)*V[s]
// ---------------------------------------------------------------------------

#define N_NODES 50000
#define N_EDGES 600000

__device__ float g_qkv[(size_t)N_NODES * 384];      // 76.8 MB

#define KC      32
#define APAD    36
#define BPAD    132
#define A_CHUNK_BYTES (128 * APAD * 4)   // 18432
#define B_BYTES       (128 * BPAD * 4)   // 67584
#define GEMM_SMEM     (B_BYTES + 2 * A_CHUNK_BYTES)        // 104448
#define FUSED_SMEM    (GEMM_SMEM + 2 * 128 * 4)            // + snd/rcv tiles

__device__ __forceinline__ uint32_t f2tf32(float f) {
    uint32_t u;
    asm("cvt.rna.tf32.f32 %0, %1;" : "=r"(u) : "f"(f));
    return u;
}
__device__ __forceinline__ void mma_tf32(float& d0, float& d1, float& d2, float& d3,
                                         uint32_t a0, uint32_t a1, uint32_t a2, uint32_t a3,
                                         uint32_t b0, uint32_t b1)
{
    asm volatile(
        "mma.sync.aligned.m16n8k8.row.col.f32.tf32.tf32.f32 "
        "{%0,%1,%2,%3}, {%4,%5,%6,%7}, {%8,%9}, {%0,%1,%2,%3};"
        : "+f"(d0), "+f"(d1), "+f"(d2), "+f"(d3)
        : "r"(a0), "r"(a1), "r"(a2), "r"(a3), "r"(b0), "r"(b1));
}
__device__ __forceinline__ uint32_t smem_u32(const void* p) {
    uint32_t a;
    asm("{ .reg .u64 t; cvta.to.shared.u64 t, %1; cvt.u32.u64 %0, t; }"
        : "=r"(a) : "l"(p));
    return a;
}
__device__ __forceinline__ void cp_async16(uint32_t sdst, const void* gsrc, int bytes) {
    asm volatile("cp.async.cg.shared.global [%0], [%1], 16, %2;"
                 :: "r"(sdst), "l"(gsrc), "r"(bytes));
}
__device__ __forceinline__ void cp_commit() {
    asm volatile("cp.async.commit_group;" ::: "memory");
}
__device__ __forceinline__ float sigmoidf_(float x) {
    return 1.0f / (1.0f + __expf(-x));
}
// red WITHOUT memory clobber: operands are register-dependent; `out` is
// write-only in this kernel, so reordering vs other loads is safe and lets
// the compiler keep gather loads batched ahead of the reds.
__device__ __forceinline__ void red_v4(float* p, float4 m) {
    asm volatile("red.global.add.v4.f32 [%0], {%1,%2,%3,%4};"
                 :: "l"(p), "f"(m.x), "f"(m.y), "f"(m.z), "f"(m.w));
}

// ===========================================================================
// Shared GEMM tile body: acc = A[row0:+128, :128] @ Wtile (tf32), no store.
// On return: acc[2][8][4] per-thread fragments; Bs still holds W (tf32).
// ===========================================================================
struct GemmCtx {
    int wid, lane, g, t, wm, wn;
};

__device__ __forceinline__
void gemm_body(const float* __restrict__ A, int M, int Wstride,
               const float* __restrict__ W, int colW0,
               int row0, char* smem, const GemmCtx& cx,
               float acc[2][8][4])
{
    uint32_t* Bs = (uint32_t*)smem;
    float* Abuf[2] = { (float*)(smem + B_BYTES),
                       (float*)(smem + B_BYTES + A_CHUNK_BYTES) };
    const uint32_t sbase = smem_u32(smem);
    const uint32_t a_s[2] = { sbase + B_BYTES, sbase + B_BYTES + A_CHUNK_BYTES };
    const int tid = threadIdx.x;

    auto copyA = [&](int chunk, uint32_t sdst) {
        #pragma unroll
        for (int j = 0; j < 4; j++) {
            const int idx = tid + j * 256;
            const int r   = idx >> 3;
            const int seg = idx & 7;
            const int gr  = row0 + r;
            const int bytes = (gr < M) ? 16 : 0;
            const int grc = (gr < M) ? gr : (M - 1);
            cp_async16(sdst + (r * APAD + seg * 4) * 4,
                       A + (size_t)grc * 128 + chunk * KC + seg * 4, bytes);
        }
    };

    copyA(0, a_s[0]); cp_commit();

    #pragma unroll
    for (int it = 0; it < 16; it++) {
        const int idx = tid + it * 256;
        const int k   = idx >> 5;
        const int n4  = (idx & 31) * 4;
        const float4 v = *(const float4*)&W[(size_t)k * Wstride + colW0 + n4];
        uint4 o;
        o.x = f2tf32(v.x); o.y = f2tf32(v.y); o.z = f2tf32(v.z); o.w = f2tf32(v.w);
        *(uint4*)&Bs[k * BPAD + n4] = o;
    }

    copyA(1, a_s[1]); cp_commit();

    #pragma unroll
    for (int m = 0; m < 2; m++)
        #pragma unroll
        for (int n = 0; n < 8; n++)
            #pragma unroll
            for (int j = 0; j < 4; j++) acc[m][n][j] = 0.f;

    auto compute_chunk = [&](const float* __restrict__ Ab, int kb) {
        #pragma unroll
        for (int ks = 0; ks < 4; ks++) {
            const int k0 = ks * 8;
            uint32_t af[2][4];
            #pragma unroll
            for (int m = 0; m < 2; m++) {
                const int rb = cx.wm * 32 + m * 16 + cx.g;
                const float* p0 = Ab + rb * APAD + k0 + cx.t;
                const float* p1 = Ab + (rb + 8) * APAD + k0 + cx.t;
                af[m][0] = f2tf32(p0[0]);
                af[m][1] = f2tf32(p1[0]);
                af[m][2] = f2tf32(p0[4]);
                af[m][3] = f2tf32(p1[4]);
            }
            #pragma unroll
            for (int n = 0; n < 8; n++) {
                const int nidx = cx.wn * 64 + n * 8 + cx.g;
                const uint32_t b0 = Bs[(kb + k0 + cx.t) * BPAD + nidx];
                const uint32_t b1 = Bs[(kb + k0 + cx.t + 4) * BPAD + nidx];
                #pragma unroll
                for (int m = 0; m < 2; m++)
                    mma_tf32(acc[m][n][0], acc[m][n][1], acc[m][n][2], acc[m][n][3],
                             af[m][0], af[m][1], af[m][2], af[m][3], b0, b1);
            }
        }
    };

    asm volatile("cp.async.wait_group 1;" ::: "memory");
    __syncthreads();
    compute_chunk(Abuf[0], 0);
    __syncthreads();
    copyA(2, a_s[0]); cp_commit();

    asm volatile("cp.async.wait_group 1;" ::: "memory");
    __syncthreads();
    compute_chunk(Abuf[1], 32);
    __syncthreads();
    copyA(3, a_s[1]); cp_commit();

    asm volatile("cp.async.wait_group 1;" ::: "memory");
    __syncthreads();
    compute_chunk(Abuf[0], 64);

    asm volatile("cp.async.wait_group 0;" ::: "memory");
    __syncthreads();
    compute_chunk(Abuf[1], 96);
}

// ===========================================================================
// Node GEMM: writes h tile to out (bx==0) or QKV tile to g_qkv (bx>0).
// ===========================================================================
__global__ __launch_bounds__(256, 2)
void node_gemm(const float* __restrict__ nf,
               const float* __restrict__ Wk,
               const float* __restrict__ Wb,
               float* __restrict__ out,
               float* __restrict__ qkv)
{
    extern __shared__ char smem[];
    const int row0  = blockIdx.y * 128;
    const int colW0 = blockIdx.x * 128;

    GemmCtx cx;
    {
        const int tid = threadIdx.x;
        cx.wid = tid >> 5; cx.lane = tid & 31;
        cx.g = cx.lane >> 2; cx.t = cx.lane & 3;
        cx.wm = cx.wid >> 1; cx.wn = cx.wid & 1;
    }
    float acc[2][8][4];
    gemm_body(nf, N_NODES, 512, Wk, colW0, row0, smem, cx, acc);

    float2 bvs[8];
    #pragma unroll
    for (int n = 0; n < 8; n++)
        bvs[n] = *(const float2*)&Wb[colW0 + cx.wn * 64 + n * 8 + 2 * cx.t];

    float* C;
    int Cstride, colC0;
    if (blockIdx.x == 0) { C = out; Cstride = 128; colC0 = 0; }
    else                 { C = qkv; Cstride = 384; colC0 = colW0 - 128; }

    #pragma unroll
    for (int m = 0; m < 2; m++) {
        const int r0 = row0 + cx.wm * 32 + m * 16 + cx.g;
        const int r1 = r0 + 8;
        #pragma unroll
        for (int n = 0; n < 8; n++) {
            const int cc = colC0 + cx.wn * 64 + n * 8 + 2 * cx.t;
            if (r0 < N_NODES)
                *(float2*)&C[(size_t)r0 * Cstride + cc] =
                    make_float2(acc[m][n][0] + bvs[n].x, acc[m][n][1] + bvs[n].y);
            if (r1 < N_NODES)
                *(float2*)&C[(size_t)r1 * Cstride + cc] =
                    make_float2(acc[m][n][2] + bvs[n].x, acc[m][n][3] + bvs[n].y);
        }
    }
}

// ===========================================================================
// Fused edge kernel: 128 edges/CTA.
//   ep = ef@We + be (kept in SMEM), then ILP-batched gather/sigmoid/red.
// ===========================================================================
__global__ __launch_bounds__(256, 2)
void edge_fused(const float* __restrict__ ef,
                const float* __restrict__ We,
                const float* __restrict__ Web,
                const int*   __restrict__ snd,
                const int*   __restrict__ rcv,
                const float* __restrict__ qkv,
                float* __restrict__ out)
{
    extern __shared__ char smem[];
    float* ep_s  = (float*)smem;                       // reuses B region post-MMA
    int*   s_snd = (int*)(smem + GEMM_SMEM);
    int*   s_rcv = (int*)(smem + GEMM_SMEM + 128 * 4);

    const int tid  = threadIdx.x;
    const int row0 = blockIdx.x * 128;

    // stage edge indices early (tiny, overlaps GEMM loads)
    if (tid < 128) {
        const int e = row0 + tid;
        s_snd[tid] = (e < N_EDGES) ? __ldg(&snd[e]) : 0;
    } else {
        const int e = row0 + tid - 128;
        s_rcv[tid - 128] = (e < N_EDGES) ? __ldg(&rcv[e]) : 0;
    }

    GemmCtx cx;
    cx.wid = tid >> 5; cx.lane = tid & 31;
    cx.g = cx.lane >> 2; cx.t = cx.lane & 3;
    cx.wm = cx.wid >> 1; cx.wn = cx.wid & 1;

    float acc[2][8][4];
    gemm_body(ef, N_EDGES, 128, We, 0, row0, smem, cx, acc);

    // ---- park ep (+bias) into SMEM (B region is dead after last chunk) ----
    __syncthreads();
    float2 bvs[8];
    #pragma unroll
    for (int n = 0; n < 8; n++)
        bvs[n] = *(const float2*)&Web[cx.wn * 64 + n * 8 + 2 * cx.t];

    #pragma unroll
    for (int m = 0; m < 2; m++) {
        const int r0l = cx.wm * 32 + m * 16 + cx.g;
        #pragma unroll
        for (int n = 0; n < 8; n++) {
            const int cc = cx.wn * 64 + n * 8 + 2 * cx.t;
            *(float2*)&ep_s[r0l * BPAD + cc] =
                make_float2(acc[m][n][0] + bvs[n].x, acc[m][n][1] + bvs[n].y);
            *(float2*)&ep_s[(r0l + 8) * BPAD + cc] =
                make_float2(acc[m][n][2] + bvs[n].x, acc[m][n][3] + bvs[n].y);
        }
    }
    __syncthreads();

    // ---- phase C: warp handles 16 edges in 4 ILP-batched groups of 4 ----
    const int d = cx.lane * 4;
    #pragma unroll
    for (int b = 0; b < 4; b++) {
        int el[4], ss[4], rr[4];
        bool ok[4];
        #pragma unroll
        for (int i = 0; i < 4; i++) {
            el[i] = cx.wid * 16 + b * 4 + i;
            ok[i] = (row0 + el[i]) < N_EDGES;
            ss[i] = s_snd[el[i]];
            rr[i] = s_rcv[el[i]];
        }
        float4 q[4], kk[4], vv[4], epv[4];
        #pragma unroll
        for (int i = 0; i < 4; i++) {
            q[i]   = *(const float4*)&qkv[(size_t)rr[i] * 384 + d];
            kk[i]  = *(const float4*)&qkv[(size_t)ss[i] * 384 + 128 + d];
            vv[i]  = *(const float4*)&qkv[(size_t)ss[i] * 384 + 256 + d];
            epv[i] = *(const float4*)&ep_s[el[i] * BPAD + d];
        }
        #pragma unroll
        for (int i = 0; i < 4; i++) {
            float4 m;
            m.x = sigmoidf_(q[i].x + kk[i].x + epv[i].x) * vv[i].x;
            m.y = sigmoidf_(q[i].y + kk[i].y + epv[i].y) * vv[i].y;
            m.z = sigmoidf_(q[i].z + kk[i].z + epv[i].z) * vv[i].z;
            m.w = sigmoidf_(q[i].w + kk[i].w + epv[i].w) * vv[i].w;
            if (ok[i])
                red_v4(&out[(size_t)rr[i] * 128 + d], m);
        }
    }
}

// ---------------------------------------------------------------------------
// Launch
// Inputs: 0 nf[50000,128] 1 snd[600000] 2 rcv[600000] 3 ef[600000,128]
//         4 Wk[128,512] 5 Wb[512] 6 Wek[128,128] 7 Web[128]
// ---------------------------------------------------------------------------
extern "C" void kernel_launch(void* const* d_in, const int* in_sizes, int n_in,
                              void* d_out, int out_size)
{
    const float* nf   = (const float*)d_in[0];
    const int*   snd  = (const int*)  d_in[1];
    const int*   rcv  = (const int*)  d_in[2];
    const float* ef   = (const float*)d_in[3];
    const float* Wk   = (const float*)d_in[4];
    const float* Wb   = (const float*)d_in[5];
    const float* Wek  = (const float*)d_in[6];
    const float* Web  = (const float*)d_in[7];
    float* out = (float*)d_out;

    float* qkv_ptr;
    cudaGetSymbolAddress((void**)&qkv_ptr, g_qkv);

    cudaFuncSetAttribute(node_gemm,
                         cudaFuncAttributeMaxDynamicSharedMemorySize, GEMM_SMEM);
    cudaFuncSetAttribute(edge_fused,
                         cudaFuncAttributeMaxDynamicSharedMemorySize, FUSED_SMEM);

    // 1) node projection: h -> out, QKV -> g_qkv
    {
        dim3 grid(4, (N_NODES + 127) / 128);
        node_gemm<<<grid, 256, GEMM_SMEM>>>(nf, Wk, Wb, out, qkv_ptr);
    }
    // 2) fused edge projection + gated scatter
    {
        int blocks = (N_EDGES + 127) / 128;
        edge_fused<<<blocks, 256, FUSED_SMEM>>>(ef, Wek, Web, snd, rcv, qkv_ptr, out);
    }
}

// round 10
// speedup vs baseline: 1.2573x; 1.0294x over previous
#include <cuda_runtime.h>
#include <cuda_bf16.h>
#include <cstdint>

// ---------------------------------------------------------------------------
// ResidualGatedGCN — node tf32 GEMM + fused edge GEMM/scatter
// L2 policy: streams (nf, ef) evict_first; qkv gathers evict_last (cache_hint).
// ---------------------------------------------------------------------------

#define N_NODES 50000
#define N_EDGES 600000

__device__ float g_qkv[(size_t)N_NODES * 384];      // 76.8 MB

#define KC      32
#define APAD    36
#define BPAD    132
#define A_CHUNK_BYTES (128 * APAD * 4)   // 18432
#define B_BYTES       (128 * BPAD * 4)   // 67584
#define GEMM_SMEM     (B_BYTES + 2 * A_CHUNK_BYTES)        // 104448
#define FUSED_SMEM    (GEMM_SMEM + 2 * 128 * 4)

__device__ __forceinline__ uint32_t f2tf32(float f) {
    uint32_t u;
    asm("cvt.rna.tf32.f32 %0, %1;" : "=r"(u) : "f"(f));
    return u;
}
__device__ __forceinline__ void mma_tf32(float& d0, float& d1, float& d2, float& d3,
                                         uint32_t a0, uint32_t a1, uint32_t a2, uint32_t a3,
                                         uint32_t b0, uint32_t b1)
{
    asm volatile(
        "mma.sync.aligned.m16n8k8.row.col.f32.tf32.tf32.f32 "
        "{%0,%1,%2,%3}, {%4,%5,%6,%7}, {%8,%9}, {%0,%1,%2,%3};"
        : "+f"(d0), "+f"(d1), "+f"(d2), "+f"(d3)
        : "r"(a0), "r"(a1), "r"(a2), "r"(a3), "r"(b0), "r"(b1));
}
__device__ __forceinline__ uint32_t smem_u32(const void* p) {
    uint32_t a;
    asm("{ .reg .u64 t; cvta.to.shared.u64 t, %1; cvt.u32.u64 %0, t; }"
        : "=r"(a) : "l"(p));
    return a;
}
__device__ __forceinline__ uint64_t policy_evict_first() {
    uint64_t pol;
    asm("createpolicy.fractional.L2::evict_first.b64 %0, 1.0;" : "=l"(pol));
    return pol;
}
__device__ __forceinline__ uint64_t policy_evict_last() {
    uint64_t pol;
    asm("createpolicy.fractional.L2::evict_last.b64 %0, 1.0;" : "=l"(pol));
    return pol;
}
// cp.async 16B with L2 cache-policy (evict_first for streaming A tiles)
__device__ __forceinline__ void cp_async16_pol(uint32_t sdst, const void* gsrc,
                                               int bytes, uint64_t pol) {
    asm volatile("cp.async.cg.shared.global.L2::cache_hint [%0], [%1], 16, %2, %3;"
                 :: "r"(sdst), "l"(gsrc), "r"(bytes), "l"(pol));
}
__device__ __forceinline__ void cp_commit() {
    asm volatile("cp.async.commit_group;" ::: "memory");
}
// qkv gather: non-coherent v4 load with evict_last policy via cache_hint
__device__ __forceinline__ float4 ld_keep_f4(const float* p, uint64_t pol) {
    float4 v;
    asm volatile("ld.global.nc.L2::cache_hint.v4.f32 {%0,%1,%2,%3}, [%4], %5;"
                 : "=f"(v.x), "=f"(v.y), "=f"(v.z), "=f"(v.w)
                 : "l"(p), "l"(pol));
    return v;
}
__device__ __forceinline__ float sigmoidf_(float x) {
    return 1.0f / (1.0f + __expf(-x));
}
__device__ __forceinline__ void red_v4(float* p, float4 m) {
    asm volatile("red.global.add.v4.f32 [%0], {%1,%2,%3,%4};"
                 :: "l"(p), "f"(m.x), "f"(m.y), "f"(m.z), "f"(m.w));
}

// ===========================================================================
struct GemmCtx { int wid, lane, g, t, wm, wn; };

__device__ __forceinline__
void gemm_body(const float* __restrict__ A, int M, int Wstride,
               const float* __restrict__ W, int colW0,
               int row0, char* smem, const GemmCtx& cx,
               float acc[2][8][4], uint64_t pol)
{
    uint32_t* Bs = (uint32_t*)smem;
    float* Abuf[2] = { (float*)(smem + B_BYTES),
                       (float*)(smem + B_BYTES + A_CHUNK_BYTES) };
    const uint32_t sbase = smem_u32(smem);
    const uint32_t a_s[2] = { sbase + B_BYTES, sbase + B_BYTES + A_CHUNK_BYTES };
    const int tid = threadIdx.x;

    auto copyA = [&](int chunk, uint32_t sdst) {
        #pragma unroll
        for (int j = 0; j < 4; j++) {
            const int idx = tid + j * 256;
            const int r   = idx >> 3;
            const int seg = idx & 7;
            const int gr  = row0 + r;
            const int bytes = (gr < M) ? 16 : 0;
            const int grc = (gr < M) ? gr : (M - 1);
            cp_async16_pol(sdst + (r * APAD + seg * 4) * 4,
                           A + (size_t)grc * 128 + chunk * KC + seg * 4, bytes, pol);
        }
    };

    copyA(0, a_s[0]); cp_commit();

    #pragma unroll
    for (int it = 0; it < 16; it++) {
        const int idx = tid + it * 256;
        const int k   = idx >> 5;
        const int n4  = (idx & 31) * 4;
        const float4 v = *(const float4*)&W[(size_t)k * Wstride + colW0 + n4];
        uint4 o;
        o.x = f2tf32(v.x); o.y = f2tf32(v.y); o.z = f2tf32(v.z); o.w = f2tf32(v.w);
        *(uint4*)&Bs[k * BPAD + n4] = o;
    }

    copyA(1, a_s[1]); cp_commit();

    #pragma unroll
    for (int m = 0; m < 2; m++)
        #pragma unroll
        for (int n = 0; n < 8; n++)
            #pragma unroll
            for (int j = 0; j < 4; j++) acc[m][n][j] = 0.f;

    auto compute_chunk = [&](const float* __restrict__ Ab, int kb) {
        #pragma unroll
        for (int ks = 0; ks < 4; ks++) {
            const int k0 = ks * 8;
            uint32_t af[2][4];
            #pragma unroll
            for (int m = 0; m < 2; m++) {
                const int rb = cx.wm * 32 + m * 16 + cx.g;
                const float* p0 = Ab + rb * APAD + k0 + cx.t;
                const float* p1 = Ab + (rb + 8) * APAD + k0 + cx.t;
                af[m][0] = f2tf32(p0[0]);
                af[m][1] = f2tf32(p1[0]);
                af[m][2] = f2tf32(p0[4]);
                af[m][3] = f2tf32(p1[4]);
            }
            #pragma unroll
            for (int n = 0; n < 8; n++) {
                const int nidx = cx.wn * 64 + n * 8 + cx.g;
                const uint32_t b0 = Bs[(kb + k0 + cx.t) * BPAD + nidx];
                const uint32_t b1 = Bs[(kb + k0 + cx.t + 4) * BPAD + nidx];
                #pragma unroll
                for (int m = 0; m < 2; m++)
                    mma_tf32(acc[m][n][0], acc[m][n][1], acc[m][n][2], acc[m][n][3],
                             af[m][0], af[m][1], af[m][2], af[m][3], b0, b1);
            }
        }
    };

    asm volatile("cp.async.wait_group 1;" ::: "memory");
    __syncthreads();
    compute_chunk(Abuf[0], 0);
    __syncthreads();
    copyA(2, a_s[0]); cp_commit();

    asm volatile("cp.async.wait_group 1;" ::: "memory");
    __syncthreads();
    compute_chunk(Abuf[1], 32);
    __syncthreads();
    copyA(3, a_s[1]); cp_commit();

    asm volatile("cp.async.wait_group 1;" ::: "memory");
    __syncthreads();
    compute_chunk(Abuf[0], 64);

    asm volatile("cp.async.wait_group 0;" ::: "memory");
    __syncthreads();
    compute_chunk(Abuf[1], 96);
}

// ===========================================================================
__global__ __launch_bounds__(256, 2)
void node_gemm(const float* __restrict__ nf,
               const float* __restrict__ Wk,
               const float* __restrict__ Wb,
               float* __restrict__ out,
               float* __restrict__ qkv)
{
    extern __shared__ char smem[];
    const int row0  = blockIdx.y * 128;
    const int colW0 = blockIdx.x * 128;
    const uint64_t pol = policy_evict_first();

    GemmCtx cx;
    {
        const int tid = threadIdx.x;
        cx.wid = tid >> 5; cx.lane = tid & 31;
        cx.g = cx.lane >> 2; cx.t = cx.lane & 3;
        cx.wm = cx.wid >> 1; cx.wn = cx.wid & 1;
    }
    float acc[2][8][4];
    gemm_body(nf, N_NODES, 512, Wk, colW0, row0, smem, cx, acc, pol);

    float2 bvs[8];
    #pragma unroll
    for (int n = 0; n < 8; n++)
        bvs[n] = *(const float2*)&Wb[colW0 + cx.wn * 64 + n * 8 + 2 * cx.t];

    float* C;
    int Cstride, colC0;
    if (blockIdx.x == 0) { C = out; Cstride = 128; colC0 = 0; }
    else                 { C = qkv; Cstride = 384; colC0 = colW0 - 128; }

    #pragma unroll
    for (int m = 0; m < 2; m++) {
        const int r0 = row0 + cx.wm * 32 + m * 16 + cx.g;
        const int r1 = r0 + 8;
        #pragma unroll
        for (int n = 0; n < 8; n++) {
            const int cc = colC0 + cx.wn * 64 + n * 8 + 2 * cx.t;
            if (r0 < N_NODES)
                *(float2*)&C[(size_t)r0 * Cstride + cc] =
                    make_float2(acc[m][n][0] + bvs[n].x, acc[m][n][1] + bvs[n].y);
            if (r1 < N_NODES)
                *(float2*)&C[(size_t)r1 * Cstride + cc] =
                    make_float2(acc[m][n][2] + bvs[n].x, acc[m][n][3] + bvs[n].y);
        }
    }
}

// ===========================================================================
__global__ __launch_bounds__(256, 2)
void edge_fused(const float* __restrict__ ef,
                const float* __restrict__ We,
                const float* __restrict__ Web,
                const int*   __restrict__ snd,
                const int*   __restrict__ rcv,
                const float* __restrict__ qkv,
                float* __restrict__ out)
{
    extern __shared__ char smem[];
    float* ep_s  = (float*)smem;
    int*   s_snd = (int*)(smem + GEMM_SMEM);
    int*   s_rcv = (int*)(smem + GEMM_SMEM + 128 * 4);

    const int tid  = threadIdx.x;
    const int row0 = blockIdx.x * 128;
    const uint64_t pol_stream = policy_evict_first();
    const uint64_t pol_keep   = policy_evict_last();

    if (tid < 128) {
        const int e = row0 + tid;
        s_snd[tid] = (e < N_EDGES) ? __ldg(&snd[e]) : 0;
    } else {
        const int e = row0 + tid - 128;
        s_rcv[tid - 128] = (e < N_EDGES) ? __ldg(&rcv[e]) : 0;
    }

    GemmCtx cx;
    cx.wid = tid >> 5; cx.lane = tid & 31;
    cx.g = cx.lane >> 2; cx.t = cx.lane & 3;
    cx.wm = cx.wid >> 1; cx.wn = cx.wid & 1;

    float acc[2][8][4];
    gemm_body(ef, N_EDGES, 128, We, 0, row0, smem, cx, acc, pol_stream);

    // ---- park ep (+bias) into SMEM ----
    __syncthreads();
    float2 bvs[8];
    #pragma unroll
    for (int n = 0; n < 8; n++)
        bvs[n] = *(const float2*)&Web[cx.wn * 64 + n * 8 + 2 * cx.t];

    #pragma unroll
    for (int m = 0; m < 2; m++) {
        const int r0l = cx.wm * 32 + m * 16 + cx.g;
        #pragma unroll
        for (int n = 0; n < 8; n++) {
            const int cc = cx.wn * 64 + n * 8 + 2 * cx.t;
            *(float2*)&ep_s[r0l * BPAD + cc] =
                make_float2(acc[m][n][0] + bvs[n].x, acc[m][n][1] + bvs[n].y);
            *(float2*)&ep_s[(r0l + 8) * BPAD + cc] =
                make_float2(acc[m][n][2] + bvs[n].x, acc[m][n][3] + bvs[n].y);
        }
    }
    __syncthreads();

    // ---- phase C: 4-edge ILP batches, qkv loads pinned in L2 ----
    const int d = cx.lane * 4;
    #pragma unroll
    for (int b = 0; b < 4; b++) {
        int el[4], ss[4], rr[4];
        bool ok[4];
        #pragma unroll
        for (int i = 0; i < 4; i++) {
            el[i] = cx.wid * 16 + b * 4 + i;
            ok[i] = (row0 + el[i]) < N_EDGES;
            ss[i] = s_snd[el[i]];
            rr[i] = s_rcv[el[i]];
        }
        float4 q[4], kk[4], vv[4], epv[4];
        #pragma unroll
        for (int i = 0; i < 4; i++) {
            q[i]   = ld_keep_f4(&qkv[(size_t)rr[i] * 384 + d], pol_keep);
            kk[i]  = ld_keep_f4(&qkv[(size_t)ss[i] * 384 + 128 + d], pol_keep);
            vv[i]  = ld_keep_f4(&qkv[(size_t)ss[i] * 384 + 256 + d], pol_keep);
            epv[i] = *(const float4*)&ep_s[el[i] * BPAD + d];
        }
        #pragma unroll
        for (int i = 0; i < 4; i++) {
            float4 m;
            m.x = sigmoidf_(q[i].x + kk[i].x + epv[i].x) * vv[i].x;
            m.y = sigmoidf_(q[i].y + kk[i].y + epv[i].y) * vv[i].y;
            m.z = sigmoidf_(q[i].z + kk[i].z + epv[i].z) * vv[i].z;
            m.w = sigmoidf_(q[i].w + kk[i].w + epv[i].w) * vv[i].w;
            if (ok[i])
                red_v4(&out[(size_t)rr[i] * 128 + d], m);
        }
    }
}

// ---------------------------------------------------------------------------
// Launch
// Inputs: 0 nf[50000,128] 1 snd[600000] 2 rcv[600000] 3 ef[600000,128]
//         4 Wk[128,512] 5 Wb[512] 6 Wek[128,128] 7 Web[128]
// ---------------------------------------------------------------------------
extern "C" void kernel_launch(void* const* d_in, const int* in_sizes, int n_in,
                              void* d_out, int out_size)
{
    const float* nf   = (const float*)d_in[0];
    const int*   snd  = (const int*)  d_in[1];
    const int*   rcv  = (const int*)  d_in[2];
    const float* ef   = (const float*)d_in[3];
    const float* Wk   = (const float*)d_in[4];
    const float* Wb   = (const float*)d_in[5];
    const float* Wek  = (const float*)d_in[6];
    const float* Web  = (const float*)d_in[7];
    float* out = (float*)d_out;

    float* qkv_ptr;
    cudaGetSymbolAddress((void**)&qkv_ptr, g_qkv);

    cudaFuncSetAttribute(node_gemm,
                         cudaFuncAttributeMaxDynamicSharedMemorySize, GEMM_SMEM);
    cudaFuncSetAttribute(edge_fused,
                         cudaFuncAttributeMaxDynamicSharedMemorySize, FUSED_SMEM);

    {
        dim3 grid(4, (N_NODES + 127) / 128);
        node_gemm<<<grid, 256, GEMM_SMEM>>>(nf, Wk, Wb, out, qkv_ptr);
    }
    {
        int blocks = (N_EDGES + 127) / 128;
        edge_fused<<<blocks, 256, FUSED_SMEM>>>(ef, Wek, Web, snd, rcv, qkv_ptr, out);
    }
}